// round 9
// baseline (speedup 1.0000x reference)
#include <cuda_runtime.h>
#include <cuda_fp16.h>

#define NN 100000
#define NE 1600000
#define NG 512
#define NOUT 10
#define NB_SCAN ((NN + 1023) / 1024)     // 98
#define NB_ZERO ((NN + 255) / 256)       // 391

// GEMM geometry: CTA = 128x64 output, 8 warps (4x2), warp tile 32x32
#define SA_A 40                         // A smem row stride (halves)
#define SA_W 72                         // W smem row stride (halves)
#define A_STAGE (128 * SA_A)
#define W_STAGE (32 * SA_W)
#define STAGE_HALVES (2 * A_STAGE + 2 * W_STAGE)
#define SMEM_BYTES (2 * STAGE_HALVES * 2)   // 59392 B

// ---------------- scratch (device globals; no allocation allowed) ----------
__device__ __align__(16) __half g_gh[(size_t)NN * 128];   // g = dinv*(h@W), fp16
__device__ __align__(16) __half g_ah[(size_t)NN * 128];   // activation hi half
__device__ __align__(16) __half g_al[(size_t)NN * 128];   // activation lo half
__device__ __align__(16) __half g_wh[4 * 128 * 128];      // weights hi (4 layers)
__device__ __align__(16) __half g_wl[4 * 128 * 128];      // weights lo
__device__ __align__(16) int    g_deg[NN];
__device__ __align__(16) int    g_fill[NN];
__device__ __align__(16) int    g_off[NN + 1];
__device__ __align__(16) unsigned long long g_scanstate[128];
__device__ __align__(16) int    g_csr[NE];

// ---------------- helpers ----------------------------------------------------
__device__ __forceinline__ void split2(float a, float b, unsigned& hi, unsigned& lo) {
    __half h0 = __float2half_rn(a), h1 = __float2half_rn(b);
    __half l0 = __float2half_rn(a - __half2float(h0));
    __half l1 = __float2half_rn(b - __half2float(h1));
    __half2 H = __halves2half2(h0, h1), L = __halves2half2(l0, l1);
    hi = *(unsigned*)&H; lo = *(unsigned*)&L;
}

__device__ __forceinline__ void mma16816(float* c, const unsigned* a, const unsigned* b) {
    asm volatile(
        "mma.sync.aligned.m16n8k16.row.col.f32.f16.f16.f32 "
        "{%0,%1,%2,%3}, {%4,%5,%6,%7}, {%8,%9}, {%0,%1,%2,%3};"
        : "+f"(c[0]), "+f"(c[1]), "+f"(c[2]), "+f"(c[3])
        : "r"(a[0]), "r"(a[1]), "r"(a[2]), "r"(a[3]), "r"(b[0]), "r"(b[1]));
}

__device__ __forceinline__ void cpa16(__half* dst_smem, const __half* src) {
    unsigned d = (unsigned)__cvta_generic_to_shared(dst_smem);
    asm volatile("cp.async.cg.shared.global [%0], [%1], 16;" :: "r"(d), "l"(src));
}

__device__ __forceinline__ void ldsm_x4(unsigned* r, const __half* p) {
    unsigned a = (unsigned)__cvta_generic_to_shared(p);
    asm volatile("ldmatrix.sync.aligned.m8n8.x4.shared.b16 {%0,%1,%2,%3}, [%4];"
                 : "=r"(r[0]), "=r"(r[1]), "=r"(r[2]), "=r"(r[3]) : "r"(a));
}

__device__ __forceinline__ void ldsm_x4t(unsigned* r, const __half* p) {
    unsigned a = (unsigned)__cvta_generic_to_shared(p);
    asm volatile("ldmatrix.sync.aligned.m8n8.x4.trans.shared.b16 {%0,%1,%2,%3}, [%4];"
                 : "=r"(r[0]), "=r"(r[1]), "=r"(r[2]), "=r"(r[3]) : "r"(a));
}

// ---------------- init: zero deg + scan state, split weights -----------------
__global__ void k_init(const float* __restrict__ W_in,
                       const float* __restrict__ W_hid) {
    if (blockIdx.x < NB_ZERO) {
        int i = blockIdx.x * 256 + threadIdx.x;
        if (i < NN) g_deg[i] = 0;
        if (blockIdx.x == 0 && threadIdx.x < 128) g_scanstate[threadIdx.x] = 0ULL;
    } else {
        size_t wi = (size_t)(blockIdx.x - NB_ZERO) * 256 + threadIdx.x;  // float4
        if (wi < 16384) {
            float4 v = (wi < 4096) ? ((const float4*)W_in)[wi]
                                   : ((const float4*)W_hid)[wi - 4096];
            uint2 hi, lo;
            split2(v.x, v.y, hi.x, lo.x);
            split2(v.z, v.w, hi.y, lo.y);
            *(uint2*)(g_wh + wi * 4) = hi;
            *(uint2*)(g_wl + wi * 4) = lo;
        }
    }
}

__global__ void k_edge_prep(const int* __restrict__ ei) {
    int t = blockIdx.x * blockDim.x + threadIdx.x;
    if (t < NE / 4) {
        int4 d = ((const int4*)(ei + NE))[t];
        atomicAdd(&g_deg[d.x], 1);
        atomicAdd(&g_deg[d.y], 1);
        atomicAdd(&g_deg[d.z], 1);
        atomicAdd(&g_deg[d.w], 1);
    }
}

// ---------------- fused scan (decoupled lookback): off + fill seed ----------
__global__ void k_scan_fused() {
    __shared__ int sm[1024];
    __shared__ int s_prefix;
    const int b = blockIdx.x;
    const int i = b * 1024 + threadIdx.x;
    const int v = (i < NN) ? g_deg[i] : 0;
    sm[threadIdx.x] = v;
    __syncthreads();
    for (int d = 1; d < 1024; d <<= 1) {
        int t = (threadIdx.x >= d) ? sm[threadIdx.x - d] : 0;
        __syncthreads();
        sm[threadIdx.x] += t;
        __syncthreads();
    }
    if (threadIdx.x == 0) {
        const unsigned total = (unsigned)sm[1023];
        if (b == 0) {
            atomicExch(&g_scanstate[0], (2ULL << 32) | total);   // inclusive
            s_prefix = 0;
        } else {
            atomicExch(&g_scanstate[b], (1ULL << 32) | total);   // aggregate
            int excl = 0;
            int pb = b - 1;
            while (true) {
                unsigned long long st = atomicAdd(&g_scanstate[pb], 0ULL);
                unsigned flag = (unsigned)(st >> 32);
                if (flag == 0) continue;                          // spin
                excl += (int)(st & 0xffffffffu);
                if (flag == 2u) break;
                pb--;
            }
            atomicExch(&g_scanstate[b], (2ULL << 32) | (unsigned)(total + excl));
            s_prefix = excl;
        }
    }
    __syncthreads();
    const int incl = sm[threadIdx.x] + s_prefix;
    if (i < NN) {
        int excl_i = incl - v;
        g_off[i]  = excl_i;
        g_fill[i] = excl_i;
        if (i == NN - 1) g_off[NN] = incl;
    }
}

__global__ void k_fill(const int* __restrict__ ei) {
    int t = blockIdx.x * blockDim.x + threadIdx.x;
    if (t < NE / 4) {
        int4 s = ((const int4*)ei)[t];
        int4 d = ((const int4*)(ei + NE))[t];
        int p;
        p = atomicAdd(&g_fill[d.x], 1); g_csr[p] = s.x;
        p = atomicAdd(&g_fill[d.y], 1); g_csr[p] = s.y;
        p = atomicAdd(&g_fill[d.z], 1); g_csr[p] = s.z;
        p = atomicAdd(&g_fill[d.w], 1); g_csr[p] = s.w;
    }
}

// ---------------- tensor-core GEMM: g = fp16( dinv * (A @ W) ) ---------------
// CTA = 128x64 output; grid = rowTiles*2 (blockIdx.x&1 selects col half).
// 8 warps 4x2, warp tile 32x32.  K chunks of 32, 2-stage cp.async. 3 CTAs/SM.
// Layer 0 (use_ext): A loaded fp32 from x and split in-kernel.
__global__ void __launch_bounds__(256, 3) k_gemm_tc(int layer,
                                                    const float* __restrict__ Aext,
                                                    int use_ext) {
    extern __shared__ __half smh[];
    const int col0 = (blockIdx.x & 1) * 64;
    const int row0 = (blockIdx.x >> 1) * 128;
    const __half* Wbh = g_wh + (size_t)layer * 16384 + col0;
    const __half* Wbl = g_wl + (size_t)layer * 16384 + col0;
    const int tid = threadIdx.x;

    __half* Ah[2]; __half* Al[2]; __half* Wh[2]; __half* Wl[2];
#pragma unroll
    for (int s = 0; s < 2; s++) {
        __half* base = smh + s * STAGE_HALVES;
        Ah[s] = base;
        Al[s] = base + A_STAGE;
        Wh[s] = base + 2 * A_STAGE;
        Wl[s] = base + 2 * A_STAGE + W_STAGE;
    }

    auto prefetch = [&](int c, int s) {
        const int k0 = c * 32;
        if (use_ext) {
            // fp32 direct load + split (layer 0); 2 segs of 8 cols per thread
#pragma unroll
            for (int o = tid; o < 512; o += 256) {
                int r = o >> 2, seg = (o & 3) * 8;
                int grow = row0 + r;
                if (grow < NN) {
                    const float* src = Aext + (size_t)grow * 128 + k0 + seg;
                    float4 v0 = *(const float4*)(src);
                    float4 v1 = *(const float4*)(src + 4);
                    uint2 h0, l0, h1, l1;
                    split2(v0.x, v0.y, h0.x, l0.x);
                    split2(v0.z, v0.w, h0.y, l0.y);
                    split2(v1.x, v1.y, h1.x, l1.x);
                    split2(v1.z, v1.w, h1.y, l1.y);
                    *(uint2*)(Ah[s] + r * SA_A + seg)     = h0;
                    *(uint2*)(Ah[s] + r * SA_A + seg + 4) = h1;
                    *(uint2*)(Al[s] + r * SA_A + seg)     = l0;
                    *(uint2*)(Al[s] + r * SA_A + seg + 4) = l1;
                }
            }
        } else {
#pragma unroll
            for (int o = tid; o < 512; o += 256) {           // A: 128 rows x 4 segs
                int r = o >> 2, seg = (o & 3) * 8;
                int grow = row0 + r;
                if (grow < NN) {
                    cpa16(Ah[s] + r * SA_A + seg, g_ah + (size_t)grow * 128 + k0 + seg);
                    cpa16(Al[s] + r * SA_A + seg, g_al + (size_t)grow * 128 + k0 + seg);
                }
            }
        }
        {                                                     // W: 32 rows x 8 segs
            int kr = tid >> 3, seg = (tid & 7) * 8;
            cpa16(Wh[s] + kr * SA_W + seg, Wbh + (size_t)(k0 + kr) * 128 + seg);
            cpa16(Wl[s] + kr * SA_W + seg, Wbl + (size_t)(k0 + kr) * 128 + seg);
        }
        asm volatile("cp.async.commit_group;");
    };

    const int lane = tid & 31, wid = tid >> 5;
    const int wm = wid >> 1, wn = wid & 1;               // 4x2 warp grid
    const int g = lane >> 2, t2 = (lane & 3) << 1;
    const int lr = lane & 7, sel = lane >> 3;
    const int a_row_off = (sel & 1) * 8;
    const int a_col_off = (sel & 2) * 4;
    const int w_krow = lane & 15;
    const int w_noff = (lane >> 4) * 8;

    float acc[2][4][4];
#pragma unroll
    for (int mt = 0; mt < 2; mt++)
#pragma unroll
        for (int nt = 0; nt < 4; nt++)
#pragma unroll
            for (int q = 0; q < 4; q++) acc[mt][nt][q] = 0.f;

    prefetch(0, 0);
    prefetch(1, 1);

#pragma unroll
    for (int c = 0; c < 4; c++) {
        const int s = c & 1;
        if (c < 3) asm volatile("cp.async.wait_group 1;");
        else       asm volatile("cp.async.wait_group 0;");
        __syncthreads();

#pragma unroll
        for (int ks = 0; ks < 2; ks++) {
            const int kc = ks * 16;
            unsigned bh2[2][4], bl2[2][4];
#pragma unroll
            for (int nh = 0; nh < 2; nh++) {
                const __half* pw = Wh[s] + (kc + w_krow) * SA_W + wn * 32 + nh * 16 + w_noff;
                ldsm_x4t(bh2[nh], pw);
                const __half* pl = Wl[s] + (kc + w_krow) * SA_W + wn * 32 + nh * 16 + w_noff;
                ldsm_x4t(bl2[nh], pl);
            }
#pragma unroll
            for (int mt = 0; mt < 2; mt++) {
                const int m0 = wm * 32 + mt * 16;
                unsigned ah_[4], al_[4];
                ldsm_x4(ah_, Ah[s] + (m0 + lr + a_row_off) * SA_A + kc + a_col_off);
                ldsm_x4(al_, Al[s] + (m0 + lr + a_row_off) * SA_A + kc + a_col_off);
#pragma unroll
                for (int nt = 0; nt < 4; nt++) {
                    unsigned bhf[2] = {bh2[nt >> 1][(nt & 1) * 2],
                                       bh2[nt >> 1][(nt & 1) * 2 + 1]};
                    unsigned blf[2] = {bl2[nt >> 1][(nt & 1) * 2],
                                       bl2[nt >> 1][(nt & 1) * 2 + 1]};
                    mma16816(acc[mt][nt], ah_, bhf);   // Ah @ Wh
                    mma16816(acc[mt][nt], ah_, blf);   // Ah @ Wl
                    mma16816(acc[mt][nt], al_, bhf);   // Al @ Wh
                }
            }
        }
        __syncthreads();
        if (c + 2 < 4) prefetch(c + 2, s);
    }

    // epilogue: scale by dinv (from deg), pack fp16, store
#pragma unroll
    for (int mt = 0; mt < 2; mt++) {
        int r0 = row0 + wm * 32 + mt * 16 + g;
        int r1 = r0 + 8;
        float d0 = (r0 < NN) ? rsqrtf((float)(g_deg[r0] + 1)) : 0.f;
        float d1 = (r1 < NN) ? rsqrtf((float)(g_deg[r1] + 1)) : 0.f;
#pragma unroll
        for (int nt = 0; nt < 4; nt++) {
            int n = col0 + wn * 32 + nt * 8 + t2;
            if (r0 < NN) {
                __half2 p = __floats2half2_rn(acc[mt][nt][0] * d0, acc[mt][nt][1] * d0);
                *(__half2*)(g_gh + (size_t)r0 * 128 + n) = p;
            }
            if (r1 < NN) {
                __half2 p = __floats2half2_rn(acc[mt][nt][2] * d1, acc[mt][nt][3] * d1);
                *(__half2*)(g_gh + (size_t)r1 * 128 + n) = p;
            }
        }
    }
}

// ---------------- aggregation (gather CSR; writes split activations) --------
__global__ void __launch_bounds__(256) k_agg(const float* __restrict__ bias) {
    int n = (blockIdx.x * blockDim.x + threadIdx.x) >> 5;
    int lane = threadIdx.x & 31;
    if (n >= NN) return;
    const uint2* gb = (const uint2*)g_gh;       // 8B units; row stride = 32
    uint2 sv = gb[(size_t)n * 32 + lane];       // self-loop term
    __half2 h0 = *(__half2*)&sv.x, h1 = *(__half2*)&sv.y;
    float2 f0 = __half22float2(h0), f1 = __half22float2(h1);
    float4 acc = make_float4(f0.x, f0.y, f1.x, f1.y);

    int s = g_off[n], e = g_off[n + 1];
    for (int base = s; base < e; base += 32) {
        int cnt = e - base; if (cnt > 32) cnt = 32;
        int id = (lane < cnt) ? g_csr[base + lane] : 0;
        int jmax = cnt & ~1;
        for (int j = 0; j < jmax; j += 2) {
            int sa = __shfl_sync(0xffffffffu, id, j);
            int sb = __shfl_sync(0xffffffffu, id, j + 1);
            uint2 va = gb[(size_t)sa * 32 + lane];
            uint2 vb = gb[(size_t)sb * 32 + lane];
            __half2 s0 = __hadd2(*(__half2*)&va.x, *(__half2*)&vb.x);
            __half2 s1 = __hadd2(*(__half2*)&va.y, *(__half2*)&vb.y);
            float2 g0 = __half22float2(s0), g1 = __half22float2(s1);
            acc.x += g0.x; acc.y += g0.y; acc.z += g1.x; acc.w += g1.y;
        }
        if (cnt & 1) {
            int sa = __shfl_sync(0xffffffffu, id, cnt - 1);
            uint2 va = gb[(size_t)sa * 32 + lane];
            float2 g0 = __half22float2(*(__half2*)&va.x);
            float2 g1 = __half22float2(*(__half2*)&va.y);
            acc.x += g0.x; acc.y += g0.y; acc.z += g1.x; acc.w += g1.y;
        }
    }
    float dn = rsqrtf((float)(g_deg[n] + 1));
    float4 bb = *(const float4*)(bias + lane * 4);
    float4 o = make_float4(acc.x * dn + bb.x, acc.y * dn + bb.y,
                           acc.z * dn + bb.z, acc.w * dn + bb.w);
    uint2 hi, lo;
    split2(o.x, o.y, hi.x, lo.x);
    split2(o.z, o.w, hi.y, lo.y);
    *(uint2*)(g_ah + (size_t)n * 128 + lane * 4) = hi;
    *(uint2*)(g_al + (size_t)n * 128 + lane * 4) = lo;
}

// ---------------- mean pool per graph + output head -------------------------
__global__ void __launch_bounds__(128) k_pool(const int* __restrict__ batch,
                                              const float* __restrict__ Wout,
                                              const float* __restrict__ bout,
                                              float* __restrict__ out) {
    int gid = blockIdx.x;
    int c = threadIdx.x;
    int lo = 0, hi = NN;
    while (lo < hi) { int m = (lo + hi) >> 1; if (batch[m] < gid) lo = m + 1; else hi = m; }
    int start = lo;
    hi = NN;
    while (lo < hi) { int m = (lo + hi) >> 1; if (batch[m] < gid + 1) lo = m + 1; else hi = m; }
    int end = lo;

    float s = 0.f;
    for (int r = start; r < end; r++)
        s += __half2float(g_ah[(size_t)r * 128 + c]) +
             __half2float(g_al[(size_t)r * 128 + c]);
    __shared__ float pooled[128];
    int cnt = end - start;
    pooled[c] = (cnt > 0) ? s / (float)cnt : 0.f;
    __syncthreads();
    if (c < NOUT) {
        float a = bout[c];
#pragma unroll 8
        for (int k = 0; k < 128; k++) a += pooled[k] * Wout[k * NOUT + c];
        out[gid * NOUT + c] = a;
    }
}

// ---------------- launch ----------------------------------------------------
extern "C" void kernel_launch(void* const* d_in, const int* in_sizes, int n_in,
                              void* d_out, int out_size) {
    const float* x      = (const float*)d_in[0];
    const int*   ei     = (const int*)d_in[1];     // int32 (JAX x64 disabled)
    const int*   batch  = (const int*)d_in[2];     // int32
    const float* W_in   = (const float*)d_in[3];
    const float* b_in   = (const float*)d_in[4];
    const float* W_hid  = (const float*)d_in[5];
    const float* b_hid  = (const float*)d_in[6];
    const float* W_out  = (const float*)d_in[7];
    const float* b_out  = (const float*)d_in[8];
    float* out = (float*)d_out;

    cudaFuncSetAttribute(k_gemm_tc, cudaFuncAttributeMaxDynamicSharedMemorySize,
                         SMEM_BYTES);

    const int gemm_blocks = ((NN + 127) / 128) * 2;   // 128x64 tiles
    const int agg_blocks  = (NN * 32 + 255) / 256;

    // gemm0 kept as 4th launch (ncu capture slot)
    k_init<<<NB_ZERO + 64, 256>>>(W_in, W_hid);
    k_edge_prep<<<(NE / 4 + 255) / 256, 256>>>(ei);
    k_scan_fused<<<NB_SCAN, 1024>>>();
    k_gemm_tc<<<gemm_blocks, 256, SMEM_BYTES>>>(0, x, 1);    // <- profiled
    k_fill<<<(NE / 4 + 255) / 256, 256>>>(ei);

    k_agg<<<agg_blocks, 256>>>(b_in);
    for (int i = 0; i < 3; i++) {
        k_gemm_tc<<<gemm_blocks, 256, SMEM_BYTES>>>(i + 1, x, 0);
        k_agg<<<agg_blocks, 256>>>(b_hid + (size_t)i * 128);
    }

    k_pool<<<NG, 128>>>(batch, W_out, b_out, out);
}

// round 10
// speedup vs baseline: 1.1885x; 1.1885x over previous
#include <cuda_runtime.h>
#include <cuda_fp16.h>

#define NN 100000
#define NE 1600000
#define NG 512
#define NOUT 10
#define NB_SCAN ((NN + 1023) / 1024)     // 98
#define NB_ZERO ((NN + 255) / 256)       // 391
#define NB_XCONV 12500                   // NN*128/4/256

// GEMM geometry: CTA = 128x64 output, 8 warps (4x2), warp tile 32x32
// A single fp16 (1 buffer), W split hi/lo (2 buffers). 3-stage cp.async.
#define SA_A 40                          // A smem row stride (halves)
#define SA_W 72                          // W smem row stride (halves)
#define A_STAGE (128 * SA_A)             // 5120 halves
#define W_STAGE (32 * SA_W)              // 2304 halves
#define STAGE_HALVES (A_STAGE + 2 * W_STAGE)   // 9728
#define NSTAGE 3
#define SMEM_BYTES (NSTAGE * STAGE_HALVES * 2) // 58368 B

// ---------------- scratch (device globals; no allocation allowed) ----------
__device__ __align__(16) __half g_gh[(size_t)NN * 128];   // g = dinv*(h@W), fp16
__device__ __align__(16) __half g_ah[(size_t)NN * 128];   // activations, fp16
__device__ __align__(16) __half g_wh[4 * 128 * 128];      // weights hi (4 layers)
__device__ __align__(16) __half g_wl[4 * 128 * 128];      // weights lo
__device__ __align__(16) int    g_deg[NN];
__device__ __align__(16) int    g_fill[NN];
__device__ __align__(16) int    g_off[NN + 1];
__device__ __align__(16) unsigned long long g_scanstate[128];
__device__ __align__(16) int    g_csr[NE];

// ---------------- helpers ----------------------------------------------------
__device__ __forceinline__ void split2(float a, float b, unsigned& hi, unsigned& lo) {
    __half h0 = __float2half_rn(a), h1 = __float2half_rn(b);
    __half l0 = __float2half_rn(a - __half2float(h0));
    __half l1 = __float2half_rn(b - __half2float(h1));
    __half2 H = __halves2half2(h0, h1), L = __halves2half2(l0, l1);
    hi = *(unsigned*)&H; lo = *(unsigned*)&L;
}

__device__ __forceinline__ void mma16816(float* c, const unsigned* a, const unsigned* b) {
    asm volatile(
        "mma.sync.aligned.m16n8k16.row.col.f32.f16.f16.f32 "
        "{%0,%1,%2,%3}, {%4,%5,%6,%7}, {%8,%9}, {%0,%1,%2,%3};"
        : "+f"(c[0]), "+f"(c[1]), "+f"(c[2]), "+f"(c[3])
        : "r"(a[0]), "r"(a[1]), "r"(a[2]), "r"(a[3]), "r"(b[0]), "r"(b[1]));
}

__device__ __forceinline__ void cpa16(__half* dst_smem, const __half* src) {
    unsigned d = (unsigned)__cvta_generic_to_shared(dst_smem);
    asm volatile("cp.async.cg.shared.global [%0], [%1], 16;" :: "r"(d), "l"(src));
}

__device__ __forceinline__ void ldsm_x4(unsigned* r, const __half* p) {
    unsigned a = (unsigned)__cvta_generic_to_shared(p);
    asm volatile("ldmatrix.sync.aligned.m8n8.x4.shared.b16 {%0,%1,%2,%3}, [%4];"
                 : "=r"(r[0]), "=r"(r[1]), "=r"(r[2]), "=r"(r[3]) : "r"(a));
}

__device__ __forceinline__ void ldsm_x4t(unsigned* r, const __half* p) {
    unsigned a = (unsigned)__cvta_generic_to_shared(p);
    asm volatile("ldmatrix.sync.aligned.m8n8.x4.trans.shared.b16 {%0,%1,%2,%3}, [%4];"
                 : "=r"(r[0]), "=r"(r[1]), "=r"(r[2]), "=r"(r[3]) : "r"(a));
}

// ---------------- init: convert x->fp16, zero deg/state, split weights -------
__global__ void k_init(const float* __restrict__ x,
                       const float* __restrict__ W_in,
                       const float* __restrict__ W_hid) {
    if (blockIdx.x < NB_XCONV) {
        size_t i = (size_t)blockIdx.x * 256 + threadIdx.x;   // float4 index
        float4 v = ((const float4*)x)[i];
        __half2 a = __floats2half2_rn(v.x, v.y);
        __half2 b = __floats2half2_rn(v.z, v.w);
        uint2 p; p.x = *(unsigned*)&a; p.y = *(unsigned*)&b;
        *(uint2*)(g_ah + i * 4) = p;
    } else if (blockIdx.x < NB_XCONV + NB_ZERO) {
        int i = (blockIdx.x - NB_XCONV) * 256 + threadIdx.x;
        if (i < NN) g_deg[i] = 0;
        if (blockIdx.x == NB_XCONV && threadIdx.x < 128) g_scanstate[threadIdx.x] = 0ULL;
    } else {
        size_t wi = (size_t)(blockIdx.x - NB_XCONV - NB_ZERO) * 256 + threadIdx.x;
        if (wi < 16384) {
            float4 v = (wi < 4096) ? ((const float4*)W_in)[wi]
                                   : ((const float4*)W_hid)[wi - 4096];
            uint2 hi, lo;
            split2(v.x, v.y, hi.x, lo.x);
            split2(v.z, v.w, hi.y, lo.y);
            *(uint2*)(g_wh + wi * 4) = hi;
            *(uint2*)(g_wl + wi * 4) = lo;
        }
    }
}

__global__ void k_edge_prep(const int* __restrict__ ei) {
    int t = blockIdx.x * blockDim.x + threadIdx.x;
    if (t < NE / 4) {
        int4 d = ((const int4*)(ei + NE))[t];
        atomicAdd(&g_deg[d.x], 1);
        atomicAdd(&g_deg[d.y], 1);
        atomicAdd(&g_deg[d.z], 1);
        atomicAdd(&g_deg[d.w], 1);
    }
}

// ---------------- fused scan (decoupled lookback): off + fill seed ----------
__global__ void k_scan_fused() {
    __shared__ int sm[1024];
    __shared__ int s_prefix;
    const int b = blockIdx.x;
    const int i = b * 1024 + threadIdx.x;
    const int v = (i < NN) ? g_deg[i] : 0;
    sm[threadIdx.x] = v;
    __syncthreads();
    for (int d = 1; d < 1024; d <<= 1) {
        int t = (threadIdx.x >= d) ? sm[threadIdx.x - d] : 0;
        __syncthreads();
        sm[threadIdx.x] += t;
        __syncthreads();
    }
    if (threadIdx.x == 0) {
        const unsigned total = (unsigned)sm[1023];
        if (b == 0) {
            atomicExch(&g_scanstate[0], (2ULL << 32) | total);   // inclusive
            s_prefix = 0;
        } else {
            atomicExch(&g_scanstate[b], (1ULL << 32) | total);   // aggregate
            int excl = 0;
            int pb = b - 1;
            while (true) {
                unsigned long long st = atomicAdd(&g_scanstate[pb], 0ULL);
                unsigned flag = (unsigned)(st >> 32);
                if (flag == 0) continue;                          // spin
                excl += (int)(st & 0xffffffffu);
                if (flag == 2u) break;
                pb--;
            }
            atomicExch(&g_scanstate[b], (2ULL << 32) | (unsigned)(total + excl));
            s_prefix = excl;
        }
    }
    __syncthreads();
    const int incl = sm[threadIdx.x] + s_prefix;
    if (i < NN) {
        int excl_i = incl - v;
        g_off[i]  = excl_i;
        g_fill[i] = excl_i;
        if (i == NN - 1) g_off[NN] = incl;
    }
}

__global__ void k_fill(const int* __restrict__ ei) {
    int t = blockIdx.x * blockDim.x + threadIdx.x;
    if (t < NE / 4) {
        int4 s = ((const int4*)ei)[t];
        int4 d = ((const int4*)(ei + NE))[t];
        int p;
        p = atomicAdd(&g_fill[d.x], 1); g_csr[p] = s.x;
        p = atomicAdd(&g_fill[d.y], 1); g_csr[p] = s.y;
        p = atomicAdd(&g_fill[d.z], 1); g_csr[p] = s.z;
        p = atomicAdd(&g_fill[d.w], 1); g_csr[p] = s.w;
    }
}

// ---------------- tensor-core GEMM: g = fp16( dinv * (A @ W) ) ---------------
// A single fp16 from g_ah; W split (g_wh + g_wl): 2-term MMA A*Wh + A*Wl.
// CTA = 128x64; 8 warps 4x2, warp tile 32x32. K chunks of 32, 3-stage cp.async.
__global__ void __launch_bounds__(256, 3) k_gemm_tc(int layer) {
    extern __shared__ __half smh[];
    const int col0 = (blockIdx.x & 1) * 64;
    const int row0 = (blockIdx.x >> 1) * 128;
    const __half* Wbh = g_wh + (size_t)layer * 16384 + col0;
    const __half* Wbl = g_wl + (size_t)layer * 16384 + col0;
    const int tid = threadIdx.x;

    __half* As[NSTAGE]; __half* Wh[NSTAGE]; __half* Wl[NSTAGE];
#pragma unroll
    for (int s = 0; s < NSTAGE; s++) {
        __half* base = smh + s * STAGE_HALVES;
        As[s] = base;
        Wh[s] = base + A_STAGE;
        Wl[s] = base + A_STAGE + W_STAGE;
    }

    auto prefetch = [&](int c, int s) {
        const int k0 = c * 32;
#pragma unroll
        for (int o = tid; o < 512; o += 256) {          // A: 128 rows x 4 segs
            int r = o >> 2, seg = (o & 3) * 8;
            int grow = row0 + r;
            if (grow < NN)
                cpa16(As[s] + r * SA_A + seg, g_ah + (size_t)grow * 128 + k0 + seg);
        }
#pragma unroll
        for (int o = tid; o < 512; o += 256) {          // W hi/lo: 32 rows x 8 segs
            int oo = o & 255;
            int kr = oo >> 3, seg = (oo & 7) * 8;
            if (o < 256)
                cpa16(Wh[s] + kr * SA_W + seg, Wbh + (size_t)(k0 + kr) * 128 + seg);
            else
                cpa16(Wl[s] + kr * SA_W + seg, Wbl + (size_t)(k0 + kr) * 128 + seg);
        }
        asm volatile("cp.async.commit_group;");
    };

    const int lane = tid & 31, wid = tid >> 5;
    const int wm = wid >> 1, wn = wid & 1;               // 4x2 warp grid
    const int g = lane >> 2, t2 = (lane & 3) << 1;
    const int lr = lane & 7, sel = lane >> 3;
    const int a_row_off = (sel & 1) * 8;
    const int a_col_off = (sel & 2) * 4;
    const int w_krow = lane & 15;
    const int w_noff = (lane >> 4) * 8;

    float acc[2][4][4];
#pragma unroll
    for (int mt = 0; mt < 2; mt++)
#pragma unroll
        for (int nt = 0; nt < 4; nt++)
#pragma unroll
            for (int q = 0; q < 4; q++) acc[mt][nt][q] = 0.f;

    prefetch(0, 0);
    prefetch(1, 1);
    prefetch(2, 2);

#pragma unroll
    for (int c = 0; c < 4; c++) {
        const int s = c % NSTAGE;
        if (c <= 1)      asm volatile("cp.async.wait_group 2;");
        else if (c == 2) asm volatile("cp.async.wait_group 1;");
        else             asm volatile("cp.async.wait_group 0;");
        __syncthreads();

#pragma unroll
        for (int ks = 0; ks < 2; ks++) {
            const int kc = ks * 16;
            unsigned bh2[2][4], bl2[2][4];
#pragma unroll
            for (int nh = 0; nh < 2; nh++) {
                const __half* pw = Wh[s] + (kc + w_krow) * SA_W + wn * 32 + nh * 16 + w_noff;
                ldsm_x4t(bh2[nh], pw);
                const __half* pl = Wl[s] + (kc + w_krow) * SA_W + wn * 32 + nh * 16 + w_noff;
                ldsm_x4t(bl2[nh], pl);
            }
#pragma unroll
            for (int mt = 0; mt < 2; mt++) {
                const int m0 = wm * 32 + mt * 16;
                unsigned a_[4];
                ldsm_x4(a_, As[s] + (m0 + lr + a_row_off) * SA_A + kc + a_col_off);
#pragma unroll
                for (int nt = 0; nt < 4; nt++) {
                    unsigned bhf[2] = {bh2[nt >> 1][(nt & 1) * 2],
                                       bh2[nt >> 1][(nt & 1) * 2 + 1]};
                    unsigned blf[2] = {bl2[nt >> 1][(nt & 1) * 2],
                                       bl2[nt >> 1][(nt & 1) * 2 + 1]};
                    mma16816(acc[mt][nt], a_, bhf);   // A @ Wh
                    mma16816(acc[mt][nt], a_, blf);   // A @ Wl
                }
            }
        }
        __syncthreads();
        if (c + NSTAGE < 4) prefetch(c + NSTAGE, s);
    }

    // epilogue: scale by dinv (from deg), pack fp16, store
#pragma unroll
    for (int mt = 0; mt < 2; mt++) {
        int r0 = row0 + wm * 32 + mt * 16 + g;
        int r1 = r0 + 8;
        float d0 = (r0 < NN) ? rsqrtf((float)(g_deg[r0] + 1)) : 0.f;
        float d1 = (r1 < NN) ? rsqrtf((float)(g_deg[r1] + 1)) : 0.f;
#pragma unroll
        for (int nt = 0; nt < 4; nt++) {
            int n = col0 + wn * 32 + nt * 8 + t2;
            if (r0 < NN) {
                __half2 p = __floats2half2_rn(acc[mt][nt][0] * d0, acc[mt][nt][1] * d0);
                *(__half2*)(g_gh + (size_t)r0 * 128 + n) = p;
            }
            if (r1 < NN) {
                __half2 p = __floats2half2_rn(acc[mt][nt][2] * d1, acc[mt][nt][3] * d1);
                *(__half2*)(g_gh + (size_t)r1 * 128 + n) = p;
            }
        }
    }
}

// ---------------- aggregation (gather CSR; writes fp16 activations) ---------
__global__ void __launch_bounds__(256) k_agg(const float* __restrict__ bias) {
    int n = (blockIdx.x * blockDim.x + threadIdx.x) >> 5;
    int lane = threadIdx.x & 31;
    if (n >= NN) return;
    const uint2* gb = (const uint2*)g_gh;       // 8B units; row stride = 32
    uint2 sv = gb[(size_t)n * 32 + lane];       // self-loop term
    __half2 h0 = *(__half2*)&sv.x, h1 = *(__half2*)&sv.y;
    float2 f0 = __half22float2(h0), f1 = __half22float2(h1);
    float4 acc = make_float4(f0.x, f0.y, f1.x, f1.y);

    int s = g_off[n], e = g_off[n + 1];
    for (int base = s; base < e; base += 32) {
        int cnt = e - base; if (cnt > 32) cnt = 32;
        int id = (lane < cnt) ? g_csr[base + lane] : 0;
        int jmax = cnt & ~1;
        for (int j = 0; j < jmax; j += 2) {
            int sa = __shfl_sync(0xffffffffu, id, j);
            int sb = __shfl_sync(0xffffffffu, id, j + 1);
            uint2 va = gb[(size_t)sa * 32 + lane];
            uint2 vb = gb[(size_t)sb * 32 + lane];
            __half2 s0 = __hadd2(*(__half2*)&va.x, *(__half2*)&vb.x);
            __half2 s1 = __hadd2(*(__half2*)&va.y, *(__half2*)&vb.y);
            float2 g0 = __half22float2(s0), g1 = __half22float2(s1);
            acc.x += g0.x; acc.y += g0.y; acc.z += g1.x; acc.w += g1.y;
        }
        if (cnt & 1) {
            int sa = __shfl_sync(0xffffffffu, id, cnt - 1);
            uint2 va = gb[(size_t)sa * 32 + lane];
            float2 g0 = __half22float2(*(__half2*)&va.x);
            float2 g1 = __half22float2(*(__half2*)&va.y);
            acc.x += g0.x; acc.y += g0.y; acc.z += g1.x; acc.w += g1.y;
        }
    }
    float dn = rsqrtf((float)(g_deg[n] + 1));
    float4 bb = *(const float4*)(bias + lane * 4);
    __half2 o0 = __floats2half2_rn(acc.x * dn + bb.x, acc.y * dn + bb.y);
    __half2 o1 = __floats2half2_rn(acc.z * dn + bb.z, acc.w * dn + bb.w);
    uint2 p; p.x = *(unsigned*)&o0; p.y = *(unsigned*)&o1;
    *(uint2*)(g_ah + (size_t)n * 128 + lane * 4) = p;
}

// ---------------- mean pool per graph + output head -------------------------
__global__ void __launch_bounds__(128) k_pool(const int* __restrict__ batch,
                                              const float* __restrict__ Wout,
                                              const float* __restrict__ bout,
                                              float* __restrict__ out) {
    int gid = blockIdx.x;
    int c = threadIdx.x;
    int lo = 0, hi = NN;
    while (lo < hi) { int m = (lo + hi) >> 1; if (batch[m] < gid) lo = m + 1; else hi = m; }
    int start = lo;
    hi = NN;
    while (lo < hi) { int m = (lo + hi) >> 1; if (batch[m] < gid + 1) lo = m + 1; else hi = m; }
    int end = lo;

    float s = 0.f;
    for (int r = start; r < end; r++)
        s += __half2float(g_ah[(size_t)r * 128 + c]);
    __shared__ float pooled[128];
    int cnt = end - start;
    pooled[c] = (cnt > 0) ? s / (float)cnt : 0.f;
    __syncthreads();
    if (c < NOUT) {
        float a = bout[c];
#pragma unroll 8
        for (int k = 0; k < 128; k++) a += pooled[k] * Wout[k * NOUT + c];
        out[gid * NOUT + c] = a;
    }
}

// ---------------- launch ----------------------------------------------------
extern "C" void kernel_launch(void* const* d_in, const int* in_sizes, int n_in,
                              void* d_out, int out_size) {
    const float* x      = (const float*)d_in[0];
    const int*   ei     = (const int*)d_in[1];     // int32 (JAX x64 disabled)
    const int*   batch  = (const int*)d_in[2];     // int32
    const float* W_in   = (const float*)d_in[3];
    const float* b_in   = (const float*)d_in[4];
    const float* W_hid  = (const float*)d_in[5];
    const float* b_hid  = (const float*)d_in[6];
    const float* W_out  = (const float*)d_in[7];
    const float* b_out  = (const float*)d_in[8];
    float* out = (float*)d_out;

    cudaFuncSetAttribute(k_gemm_tc, cudaFuncAttributeMaxDynamicSharedMemorySize,
                         SMEM_BYTES);

    const int gemm_blocks = ((NN + 127) / 128) * 2;   // 128x64 tiles
    const int agg_blocks  = (NN * 32 + 255) / 256;

    // gemm0 kept as 4th launch (ncu capture slot)
    k_init<<<NB_XCONV + NB_ZERO + 64, 256>>>(x, W_in, W_hid);
    k_edge_prep<<<(NE / 4 + 255) / 256, 256>>>(ei);
    k_scan_fused<<<NB_SCAN, 1024>>>();
    k_gemm_tc<<<gemm_blocks, 256, SMEM_BYTES>>>(0);          // <- profiled
    k_fill<<<(NE / 4 + 255) / 256, 256>>>(ei);

    k_agg<<<agg_blocks, 256>>>(b_in);
    for (int i = 0; i < 3; i++) {
        k_gemm_tc<<<gemm_blocks, 256, SMEM_BYTES>>>(i + 1);
        k_agg<<<agg_blocks, 256>>>(b_hid + (size_t)i * 128);
    }

    k_pool<<<NG, 128>>>(batch, W_out, b_out, out);
}

// round 11
// speedup vs baseline: 1.2224x; 1.0285x over previous
#include <cuda_runtime.h>
#include <cuda_fp16.h>

#define NN 100000
#define NE 1600000
#define NG 512
#define NOUT 10
#define NB_SCAN ((NN + 1023) / 1024)     // 98
#define NB_ZERO ((NN + 255) / 256)       // 391
#define NB_XCONV 12500                   // NN*128/4/256

// GEMM geometry: CTA = 128x64 output, 8 warps (4x2), warp tile 32x32.
// Whole K=128 resident in smem: A fp16 [128][136], W hi/lo [128][72] each.
#define SA_A 136                         // A smem row stride (halves)
#define SA_W 72                          // W smem row stride (halves)
#define A_HALVES (128 * SA_A)            // 17408
#define W_HALVES (128 * SA_W)            // 9216
#define SMEM_BYTES ((A_HALVES + 2 * W_HALVES) * 2)   // 71680 B

// ---------------- scratch (device globals; no allocation allowed) ----------
__device__ __align__(16) __half g_gh[(size_t)NN * 128];   // g = dinv*(h@W), fp16
__device__ __align__(16) __half g_ah[(size_t)NN * 128];   // activations, fp16
__device__ __align__(16) __half g_wh[4 * 128 * 128];      // weights hi (4 layers)
__device__ __align__(16) __half g_wl[4 * 128 * 128];      // weights lo
__device__ __align__(16) int    g_deg[NN];
__device__ __align__(16) int    g_fill[NN];
__device__ __align__(16) int    g_off[NN + 1];
__device__ __align__(16) unsigned long long g_scanstate[128];
__device__ __align__(16) int    g_csr[NE];

// ---------------- helpers ----------------------------------------------------
__device__ __forceinline__ void split2(float a, float b, unsigned& hi, unsigned& lo) {
    __half h0 = __float2half_rn(a), h1 = __float2half_rn(b);
    __half l0 = __float2half_rn(a - __half2float(h0));
    __half l1 = __float2half_rn(b - __half2float(h1));
    __half2 H = __halves2half2(h0, h1), L = __halves2half2(l0, l1);
    hi = *(unsigned*)&H; lo = *(unsigned*)&L;
}

__device__ __forceinline__ void mma16816(float* c, const unsigned* a, const unsigned* b) {
    asm volatile(
        "mma.sync.aligned.m16n8k16.row.col.f32.f16.f16.f32 "
        "{%0,%1,%2,%3}, {%4,%5,%6,%7}, {%8,%9}, {%0,%1,%2,%3};"
        : "+f"(c[0]), "+f"(c[1]), "+f"(c[2]), "+f"(c[3])
        : "r"(a[0]), "r"(a[1]), "r"(a[2]), "r"(a[3]), "r"(b[0]), "r"(b[1]));
}

__device__ __forceinline__ void cpa16(__half* dst_smem, const __half* src) {
    unsigned d = (unsigned)__cvta_generic_to_shared(dst_smem);
    asm volatile("cp.async.cg.shared.global [%0], [%1], 16;" :: "r"(d), "l"(src));
}

__device__ __forceinline__ void ldsm_x4(unsigned* r, const __half* p) {
    unsigned a = (unsigned)__cvta_generic_to_shared(p);
    asm volatile("ldmatrix.sync.aligned.m8n8.x4.shared.b16 {%0,%1,%2,%3}, [%4];"
                 : "=r"(r[0]), "=r"(r[1]), "=r"(r[2]), "=r"(r[3]) : "r"(a));
}

__device__ __forceinline__ void ldsm_x4t(unsigned* r, const __half* p) {
    unsigned a = (unsigned)__cvta_generic_to_shared(p);
    asm volatile("ldmatrix.sync.aligned.m8n8.x4.trans.shared.b16 {%0,%1,%2,%3}, [%4];"
                 : "=r"(r[0]), "=r"(r[1]), "=r"(r[2]), "=r"(r[3]) : "r"(a));
}

// ---------------- init: convert x->fp16, zero deg/state, split weights -------
__global__ void k_init(const float* __restrict__ x,
                       const float* __restrict__ W_in,
                       const float* __restrict__ W_hid) {
    if (blockIdx.x < NB_XCONV) {
        size_t i = (size_t)blockIdx.x * 256 + threadIdx.x;   // float4 index
        float4 v = ((const float4*)x)[i];
        __half2 a = __floats2half2_rn(v.x, v.y);
        __half2 b = __floats2half2_rn(v.z, v.w);
        uint2 p; p.x = *(unsigned*)&a; p.y = *(unsigned*)&b;
        *(uint2*)(g_ah + i * 4) = p;
    } else if (blockIdx.x < NB_XCONV + NB_ZERO) {
        int i = (blockIdx.x - NB_XCONV) * 256 + threadIdx.x;
        if (i < NN) g_deg[i] = 0;
        if (blockIdx.x == NB_XCONV && threadIdx.x < 128) g_scanstate[threadIdx.x] = 0ULL;
    } else {
        size_t wi = (size_t)(blockIdx.x - NB_XCONV - NB_ZERO) * 256 + threadIdx.x;
        if (wi < 16384) {
            float4 v = (wi < 4096) ? ((const float4*)W_in)[wi]
                                   : ((const float4*)W_hid)[wi - 4096];
            uint2 hi, lo;
            split2(v.x, v.y, hi.x, lo.x);
            split2(v.z, v.w, hi.y, lo.y);
            *(uint2*)(g_wh + wi * 4) = hi;
            *(uint2*)(g_wl + wi * 4) = lo;
        }
    }
}

__global__ void k_edge_prep(const int* __restrict__ ei) {
    int t = blockIdx.x * blockDim.x + threadIdx.x;
    if (t < NE / 4) {
        int4 d = ((const int4*)(ei + NE))[t];
        atomicAdd(&g_deg[d.x], 1);
        atomicAdd(&g_deg[d.y], 1);
        atomicAdd(&g_deg[d.z], 1);
        atomicAdd(&g_deg[d.w], 1);
    }
}

// ---------------- fused scan (decoupled lookback): off + fill seed ----------
__global__ void k_scan_fused() {
    __shared__ int sm[1024];
    __shared__ int s_prefix;
    const int b = blockIdx.x;
    const int i = b * 1024 + threadIdx.x;
    const int v = (i < NN) ? g_deg[i] : 0;
    sm[threadIdx.x] = v;
    __syncthreads();
    for (int d = 1; d < 1024; d <<= 1) {
        int t = (threadIdx.x >= d) ? sm[threadIdx.x - d] : 0;
        __syncthreads();
        sm[threadIdx.x] += t;
        __syncthreads();
    }
    if (threadIdx.x == 0) {
        const unsigned total = (unsigned)sm[1023];
        if (b == 0) {
            atomicExch(&g_scanstate[0], (2ULL << 32) | total);   // inclusive
            s_prefix = 0;
        } else {
            atomicExch(&g_scanstate[b], (1ULL << 32) | total);   // aggregate
            int excl = 0;
            int pb = b - 1;
            while (true) {
                unsigned long long st = atomicAdd(&g_scanstate[pb], 0ULL);
                unsigned flag = (unsigned)(st >> 32);
                if (flag == 0) continue;                          // spin
                excl += (int)(st & 0xffffffffu);
                if (flag == 2u) break;
                pb--;
            }
            atomicExch(&g_scanstate[b], (2ULL << 32) | (unsigned)(total + excl));
            s_prefix = excl;
        }
    }
    __syncthreads();
    const int incl = sm[threadIdx.x] + s_prefix;
    if (i < NN) {
        int excl_i = incl - v;
        g_off[i]  = excl_i;
        g_fill[i] = excl_i;
        if (i == NN - 1) g_off[NN] = incl;
    }
}

__global__ void k_fill(const int* __restrict__ ei) {
    int t = blockIdx.x * blockDim.x + threadIdx.x;
    if (t < NE / 4) {
        int4 s = ((const int4*)ei)[t];
        int4 d = ((const int4*)(ei + NE))[t];
        int p;
        p = atomicAdd(&g_fill[d.x], 1); g_csr[p] = s.x;
        p = atomicAdd(&g_fill[d.y], 1); g_csr[p] = s.y;
        p = atomicAdd(&g_fill[d.z], 1); g_csr[p] = s.z;
        p = atomicAdd(&g_fill[d.w], 1); g_csr[p] = s.w;
    }
}

// ---------------- tensor-core GEMM: g = fp16( dinv * (A @ W) ) ---------------
// Whole-K resident: one cp.async burst, one wait, one sync, then 8 k-steps of
// MMA with zero barriers. A fp16; W split hi/lo (2-term MMA).
// CTA = 128x64; 8 warps 4x2, warp tile 32x32. 3 CTAs/SM.
__global__ void __launch_bounds__(256, 3) k_gemm_tc(int layer) {
    extern __shared__ __half smh[];
    __half* As = smh;                        // [128][SA_A]
    __half* Wh = smh + A_HALVES;             // [128][SA_W]
    __half* Wl = smh + A_HALVES + W_HALVES;  // [128][SA_W]
    const int col0 = (blockIdx.x & 1) * 64;
    const int row0 = (blockIdx.x >> 1) * 128;
    const __half* Wbh = g_wh + (size_t)layer * 16384 + col0;
    const __half* Wbl = g_wl + (size_t)layer * 16384 + col0;
    const int tid = threadIdx.x;

    // single burst: whole A tile (128x128) + whole W hi/lo (128x64 each)
#pragma unroll
    for (int o = tid; o < 2048; o += 256) {           // A: 128 rows x 16 segs
        int r = o >> 4, seg = (o & 15) * 8;
        int grow = row0 + r;
        if (grow < NN)
            cpa16(As + r * SA_A + seg, g_ah + (size_t)grow * 128 + seg);
    }
#pragma unroll
    for (int o = tid; o < 2048; o += 256) {           // W: 128 rows x 8 segs x2
        int oo = o & 1023;
        int kr = oo >> 3, seg = (oo & 7) * 8;
        if (o < 1024)
            cpa16(Wh + kr * SA_W + seg, Wbh + (size_t)kr * 128 + seg);
        else
            cpa16(Wl + kr * SA_W + seg, Wbl + (size_t)kr * 128 + seg);
    }
    asm volatile("cp.async.commit_group;");

    const int lane = tid & 31, wid = tid >> 5;
    const int wm = wid >> 1, wn = wid & 1;               // 4x2 warp grid
    const int g = lane >> 2, t2 = (lane & 3) << 1;
    const int lr = lane & 7, sel = lane >> 3;
    const int a_row_off = (sel & 1) * 8;
    const int a_col_off = (sel & 2) * 4;
    const int w_krow = lane & 15;
    const int w_noff = (lane >> 4) * 8;

    float acc[2][4][4];
#pragma unroll
    for (int mt = 0; mt < 2; mt++)
#pragma unroll
        for (int nt = 0; nt < 4; nt++)
#pragma unroll
            for (int q = 0; q < 4; q++) acc[mt][nt][q] = 0.f;

    asm volatile("cp.async.wait_group 0;");
    __syncthreads();

#pragma unroll
    for (int ks = 0; ks < 8; ks++) {
        const int kc = ks * 16;
        unsigned bh2[2][4], bl2[2][4];
#pragma unroll
        for (int nh = 0; nh < 2; nh++) {
            const __half* pw = Wh + (kc + w_krow) * SA_W + wn * 32 + nh * 16 + w_noff;
            ldsm_x4t(bh2[nh], pw);
            const __half* pl = Wl + (kc + w_krow) * SA_W + wn * 32 + nh * 16 + w_noff;
            ldsm_x4t(bl2[nh], pl);
        }
#pragma unroll
        for (int mt = 0; mt < 2; mt++) {
            const int m0 = wm * 32 + mt * 16;
            unsigned a_[4];
            ldsm_x4(a_, As + (m0 + lr + a_row_off) * SA_A + kc + a_col_off);
#pragma unroll
            for (int nt = 0; nt < 4; nt++) {
                unsigned bhf[2] = {bh2[nt >> 1][(nt & 1) * 2],
                                   bh2[nt >> 1][(nt & 1) * 2 + 1]};
                unsigned blf[2] = {bl2[nt >> 1][(nt & 1) * 2],
                                   bl2[nt >> 1][(nt & 1) * 2 + 1]};
                mma16816(acc[mt][nt], a_, bhf);   // A @ Wh
                mma16816(acc[mt][nt], a_, blf);   // A @ Wl
            }
        }
    }

    // epilogue: scale by dinv (from deg), pack fp16, store
#pragma unroll
    for (int mt = 0; mt < 2; mt++) {
        int r0 = row0 + wm * 32 + mt * 16 + g;
        int r1 = r0 + 8;
        float d0 = (r0 < NN) ? rsqrtf((float)(g_deg[r0] + 1)) : 0.f;
        float d1 = (r1 < NN) ? rsqrtf((float)(g_deg[r1] + 1)) : 0.f;
#pragma unroll
        for (int nt = 0; nt < 4; nt++) {
            int n = col0 + wn * 32 + nt * 8 + t2;
            if (r0 < NN) {
                __half2 p = __floats2half2_rn(acc[mt][nt][0] * d0, acc[mt][nt][1] * d0);
                *(__half2*)(g_gh + (size_t)r0 * 128 + n) = p;
            }
            if (r1 < NN) {
                __half2 p = __floats2half2_rn(acc[mt][nt][2] * d1, acc[mt][nt][3] * d1);
                *(__half2*)(g_gh + (size_t)r1 * 128 + n) = p;
            }
        }
    }
}

// ---------------- aggregation (gather CSR; writes fp16 activations) ---------
__global__ void __launch_bounds__(256) k_agg(const float* __restrict__ bias) {
    int n = (blockIdx.x * blockDim.x + threadIdx.x) >> 5;
    int lane = threadIdx.x & 31;
    if (n >= NN) return;
    const uint2* gb = (const uint2*)g_gh;       // 8B units; row stride = 32
    uint2 sv = gb[(size_t)n * 32 + lane];       // self-loop term
    __half2 h0 = *(__half2*)&sv.x, h1 = *(__half2*)&sv.y;
    float2 f0 = __half22float2(h0), f1 = __half22float2(h1);
    float4 acc = make_float4(f0.x, f0.y, f1.x, f1.y);

    int s = g_off[n], e = g_off[n + 1];
    for (int base = s; base < e; base += 32) {
        int cnt = e - base; if (cnt > 32) cnt = 32;
        int id = (lane < cnt) ? g_csr[base + lane] : 0;
        int jmax = cnt & ~1;
        for (int j = 0; j < jmax; j += 2) {
            int sa = __shfl_sync(0xffffffffu, id, j);
            int sb = __shfl_sync(0xffffffffu, id, j + 1);
            uint2 va = gb[(size_t)sa * 32 + lane];
            uint2 vb = gb[(size_t)sb * 32 + lane];
            __half2 s0 = __hadd2(*(__half2*)&va.x, *(__half2*)&vb.x);
            __half2 s1 = __hadd2(*(__half2*)&va.y, *(__half2*)&vb.y);
            float2 g0 = __half22float2(s0), g1 = __half22float2(s1);
            acc.x += g0.x; acc.y += g0.y; acc.z += g1.x; acc.w += g1.y;
        }
        if (cnt & 1) {
            int sa = __shfl_sync(0xffffffffu, id, cnt - 1);
            uint2 va = gb[(size_t)sa * 32 + lane];
            float2 g0 = __half22float2(*(__half2*)&va.x);
            float2 g1 = __half22float2(*(__half2*)&va.y);
            acc.x += g0.x; acc.y += g0.y; acc.z += g1.x; acc.w += g1.y;
        }
    }
    float dn = rsqrtf((float)(g_deg[n] + 1));
    float4 bb = *(const float4*)(bias + lane * 4);
    __half2 o0 = __floats2half2_rn(acc.x * dn + bb.x, acc.y * dn + bb.y);
    __half2 o1 = __floats2half2_rn(acc.z * dn + bb.z, acc.w * dn + bb.w);
    uint2 p; p.x = *(unsigned*)&o0; p.y = *(unsigned*)&o1;
    *(uint2*)(g_ah + (size_t)n * 128 + lane * 4) = p;
}

// ---------------- mean pool per graph + output head -------------------------
__global__ void __launch_bounds__(128) k_pool(const int* __restrict__ batch,
                                              const float* __restrict__ Wout,
                                              const float* __restrict__ bout,
                                              float* __restrict__ out) {
    int gid = blockIdx.x;
    int c = threadIdx.x;
    int lo = 0, hi = NN;
    while (lo < hi) { int m = (lo + hi) >> 1; if (batch[m] < gid) lo = m + 1; else hi = m; }
    int start = lo;
    hi = NN;
    while (lo < hi) { int m = (lo + hi) >> 1; if (batch[m] < gid + 1) lo = m + 1; else hi = m; }
    int end = lo;

    float s = 0.f;
    for (int r = start; r < end; r++)
        s += __half2float(g_ah[(size_t)r * 128 + c]);
    __shared__ float pooled[128];
    int cnt = end - start;
    pooled[c] = (cnt > 0) ? s / (float)cnt : 0.f;
    __syncthreads();
    if (c < NOUT) {
        float a = bout[c];
#pragma unroll 8
        for (int k = 0; k < 128; k++) a += pooled[k] * Wout[k * NOUT + c];
        out[gid * NOUT + c] = a;
    }
}

// ---------------- launch ----------------------------------------------------
extern "C" void kernel_launch(void* const* d_in, const int* in_sizes, int n_in,
                              void* d_out, int out_size) {
    const float* x      = (const float*)d_in[0];
    const int*   ei     = (const int*)d_in[1];     // int32 (JAX x64 disabled)
    const int*   batch  = (const int*)d_in[2];     // int32
    const float* W_in   = (const float*)d_in[3];
    const float* b_in   = (const float*)d_in[4];
    const float* W_hid  = (const float*)d_in[5];
    const float* b_hid  = (const float*)d_in[6];
    const float* W_out  = (const float*)d_in[7];
    const float* b_out  = (const float*)d_in[8];
    float* out = (float*)d_out;

    cudaFuncSetAttribute(k_gemm_tc, cudaFuncAttributeMaxDynamicSharedMemorySize,
                         SMEM_BYTES);

    const int gemm_blocks = ((NN + 127) / 128) * 2;   // 128x64 tiles
    const int agg_blocks  = (NN * 32 + 255) / 256;

    // gemm0 kept as 4th launch (ncu capture slot)
    k_init<<<NB_XCONV + NB_ZERO + 64, 256>>>(x, W_in, W_hid);
    k_edge_prep<<<(NE / 4 + 255) / 256, 256>>>(ei);
    k_scan_fused<<<NB_SCAN, 1024>>>();
    k_gemm_tc<<<gemm_blocks, 256, SMEM_BYTES>>>(0);          // <- profiled
    k_fill<<<(NE / 4 + 255) / 256, 256>>>(ei);

    k_agg<<<agg_blocks, 256>>>(b_in);
    for (int i = 0; i < 3; i++) {
        k_gemm_tc<<<gemm_blocks, 256, SMEM_BYTES>>>(i + 1);
        k_agg<<<agg_blocks, 256>>>(b_hid + (size_t)i * 128);
    }

    k_pool<<<NG, 128>>>(batch, W_out, b_out, out);
}

// round 13
// speedup vs baseline: 1.2275x; 1.0042x over previous
#include <cuda_runtime.h>
#include <cuda_fp16.h>

#define NN 100000
#define NE 1600000
#define NG 512
#define NOUT 10
#define NB_SCAN ((NN + 1023) / 1024)     // 98
#define NB_ZERO ((NN + 255) / 256)       // 391
#define NB_XCONV 12500                   // NN*128/4/256

// GEMM geometry: CTA = 128x64 output, 8 warps (4x2), warp tile 32x32.
// Whole K=128 resident in smem: A fp16 [128][136], W hi/lo [128][72] each.
#define SA_A 136                         // A smem row stride (halves)
#define SA_W 72                          // W smem row stride (halves)
#define A_HALVES (128 * SA_A)            // 17408
#define W_HALVES (128 * SA_W)            // 9216
#define SMEM_BYTES ((A_HALVES + 2 * W_HALVES) * 2)   // 71680 B

// ---------------- scratch (device globals; no allocation allowed) ----------
__device__ __align__(16) __half g_gh[(size_t)NN * 128];   // g = dinv*(h@W), fp16
__device__ __align__(16) __half g_ah[(size_t)NN * 128];   // activations, fp16
__device__ __align__(16) __half g_wh[4 * 128 * 128];      // weights hi (4 layers)
__device__ __align__(16) __half g_wl[4 * 128 * 128];      // weights lo
__device__ __align__(16) int    g_deg[NN];
__device__ __align__(16) int    g_fill[NN];
__device__ __align__(16) int    g_off[NN + 1];
__device__ __align__(16) unsigned long long g_scanstate[128];
__device__ __align__(16) int    g_csr[NE];

// ---------------- helpers ----------------------------------------------------
__device__ __forceinline__ void split2(float a, float b, unsigned& hi, unsigned& lo) {
    __half h0 = __float2half_rn(a), h1 = __float2half_rn(b);
    __half l0 = __float2half_rn(a - __half2float(h0));
    __half l1 = __float2half_rn(b - __half2float(h1));
    __half2 H = __halves2half2(h0, h1), L = __halves2half2(l0, l1);
    hi = *(unsigned*)&H; lo = *(unsigned*)&L;
}

__device__ __forceinline__ void mma16816(float* c, const unsigned* a, const unsigned* b) {
    asm volatile(
        "mma.sync.aligned.m16n8k16.row.col.f32.f16.f16.f32 "
        "{%0,%1,%2,%3}, {%4,%5,%6,%7}, {%8,%9}, {%0,%1,%2,%3};"
        : "+f"(c[0]), "+f"(c[1]), "+f"(c[2]), "+f"(c[3])
        : "r"(a[0]), "r"(a[1]), "r"(a[2]), "r"(a[3]), "r"(b[0]), "r"(b[1]));
}

__device__ __forceinline__ void cpa16(__half* dst_smem, const __half* src) {
    unsigned d = (unsigned)__cvta_generic_to_shared(dst_smem);
    asm volatile("cp.async.cg.shared.global [%0], [%1], 16;" :: "r"(d), "l"(src));
}

__device__ __forceinline__ void ldsm_x4(unsigned* r, const __half* p) {
    unsigned a = (unsigned)__cvta_generic_to_shared(p);
    asm volatile("ldmatrix.sync.aligned.m8n8.x4.shared.b16 {%0,%1,%2,%3}, [%4];"
                 : "=r"(r[0]), "=r"(r[1]), "=r"(r[2]), "=r"(r[3]) : "r"(a));
}

__device__ __forceinline__ void ldsm_x4t(unsigned* r, const __half* p) {
    unsigned a = (unsigned)__cvta_generic_to_shared(p);
    asm volatile("ldmatrix.sync.aligned.m8n8.x4.trans.shared.b16 {%0,%1,%2,%3}, [%4];"
                 : "=r"(r[0]), "=r"(r[1]), "=r"(r[2]), "=r"(r[3]) : "r"(a));
}

// ---------------- zero: deg + scan state -------------------------------------
__global__ void k_zero() {
    int i = blockIdx.x * 256 + threadIdx.x;
    if (i < NN) g_deg[i] = 0;
    if (blockIdx.x == 0 && threadIdx.x < 128) g_scanstate[threadIdx.x] = 0ULL;
}

// ---------------- conv: x->fp16 + split weights ------------------------------
__global__ void k_conv(const float* __restrict__ x,
                       const float* __restrict__ W_in,
                       const float* __restrict__ W_hid) {
    if (blockIdx.x < NB_XCONV) {
        size_t i = (size_t)blockIdx.x * 256 + threadIdx.x;   // float4 index
        float4 v = ((const float4*)x)[i];
        __half2 a = __floats2half2_rn(v.x, v.y);
        __half2 b = __floats2half2_rn(v.z, v.w);
        uint2 p; p.x = *(unsigned*)&a; p.y = *(unsigned*)&b;
        *(uint2*)(g_ah + i * 4) = p;
    } else {
        size_t wi = (size_t)(blockIdx.x - NB_XCONV) * 256 + threadIdx.x;
        if (wi < 16384) {
            float4 v = (wi < 4096) ? ((const float4*)W_in)[wi]
                                   : ((const float4*)W_hid)[wi - 4096];
            uint2 hi, lo;
            split2(v.x, v.y, hi.x, lo.x);
            split2(v.z, v.w, hi.y, lo.y);
            *(uint2*)(g_wh + wi * 4) = hi;
            *(uint2*)(g_wl + wi * 4) = lo;
        }
    }
}

__global__ void k_edge_prep(const int* __restrict__ ei) {
    int t = blockIdx.x * blockDim.x + threadIdx.x;
    if (t < NE / 4) {
        int4 d = ((const int4*)(ei + NE))[t];
        atomicAdd(&g_deg[d.x], 1);
        atomicAdd(&g_deg[d.y], 1);
        atomicAdd(&g_deg[d.z], 1);
        atomicAdd(&g_deg[d.w], 1);
    }
}

// ---------------- fused scan (decoupled lookback): off + fill seed ----------
__global__ void k_scan_fused() {
    __shared__ int sm[1024];
    __shared__ int s_prefix;
    const int b = blockIdx.x;
    const int i = b * 1024 + threadIdx.x;
    const int v = (i < NN) ? g_deg[i] : 0;
    sm[threadIdx.x] = v;
    __syncthreads();
    for (int d = 1; d < 1024; d <<= 1) {
        int t = (threadIdx.x >= d) ? sm[threadIdx.x - d] : 0;
        __syncthreads();
        sm[threadIdx.x] += t;
        __syncthreads();
    }
    if (threadIdx.x == 0) {
        const unsigned total = (unsigned)sm[1023];
        if (b == 0) {
            atomicExch(&g_scanstate[0], (2ULL << 32) | total);   // inclusive
            s_prefix = 0;
        } else {
            atomicExch(&g_scanstate[b], (1ULL << 32) | total);   // aggregate
            int excl = 0;
            int pb = b - 1;
            while (true) {
                unsigned long long st = atomicAdd(&g_scanstate[pb], 0ULL);
                unsigned flag = (unsigned)(st >> 32);
                if (flag == 0) continue;                          // spin
                excl += (int)(st & 0xffffffffu);
                if (flag == 2u) break;
                pb--;
            }
            atomicExch(&g_scanstate[b], (2ULL << 32) | (unsigned)(total + excl));
            s_prefix = excl;
        }
    }
    __syncthreads();
    const int incl = sm[threadIdx.x] + s_prefix;
    if (i < NN) {
        int excl_i = incl - v;
        g_off[i]  = excl_i;
        g_fill[i] = excl_i;
        if (i == NN - 1) g_off[NN] = incl;
    }
}

__global__ void k_fill(const int* __restrict__ ei) {
    int t = blockIdx.x * blockDim.x + threadIdx.x;
    if (t < NE / 4) {
        int4 s = ((const int4*)ei)[t];
        int4 d = ((const int4*)(ei + NE))[t];
        int p;
        p = atomicAdd(&g_fill[d.x], 1); g_csr[p] = s.x;
        p = atomicAdd(&g_fill[d.y], 1); g_csr[p] = s.y;
        p = atomicAdd(&g_fill[d.z], 1); g_csr[p] = s.z;
        p = atomicAdd(&g_fill[d.w], 1); g_csr[p] = s.w;
    }
}

// ---------------- tensor-core GEMM: g = fp16( dinv * (A @ W) ) ---------------
// Whole-K resident: one cp.async burst, one wait, one sync, then 8 k-steps of
// MMA with zero barriers. A fp16; W split hi/lo (2-term MMA).
// CTA = 128x64; 8 warps 4x2, warp tile 32x32. 3 CTAs/SM.
__global__ void __launch_bounds__(256, 3) k_gemm_tc(int layer) {
    extern __shared__ __half smh[];
    __half* As = smh;                        // [128][SA_A]
    __half* Wh = smh + A_HALVES;             // [128][SA_W]
    __half* Wl = smh + A_HALVES + W_HALVES;  // [128][SA_W]
    const int col0 = (blockIdx.x & 1) * 64;
    const int row0 = (blockIdx.x >> 1) * 128;
    const __half* Wbh = g_wh + (size_t)layer * 16384 + col0;
    const __half* Wbl = g_wl + (size_t)layer * 16384 + col0;
    const int tid = threadIdx.x;

    // single burst: whole A tile (128x128) + whole W hi/lo (128x64 each)
#pragma unroll
    for (int o = tid; o < 2048; o += 256) {           // A: 128 rows x 16 segs
        int r = o >> 4, seg = (o & 15) * 8;
        int grow = row0 + r;
        if (grow < NN)
            cpa16(As + r * SA_A + seg, g_ah + (size_t)grow * 128 + seg);
    }
#pragma unroll
    for (int o = tid; o < 2048; o += 256) {           // W: 128 rows x 8 segs x2
        int oo = o & 1023;
        int kr = oo >> 3, seg = (oo & 7) * 8;
        if (o < 1024)
            cpa16(Wh + kr * SA_W + seg, Wbh + (size_t)kr * 128 + seg);
        else
            cpa16(Wl + kr * SA_W + seg, Wbl + (size_t)kr * 128 + seg);
    }
    asm volatile("cp.async.commit_group;");

    const int lane = tid & 31, wid = tid >> 5;
    const int wm = wid >> 1, wn = wid & 1;               // 4x2 warp grid
    const int g = lane >> 2, t2 = (lane & 3) << 1;
    const int lr = lane & 7, sel = lane >> 3;
    const int a_row_off = (sel & 1) * 8;
    const int a_col_off = (sel & 2) * 4;
    const int w_krow = lane & 15;
    const int w_noff = (lane >> 4) * 8;

    float acc[2][4][4];
#pragma unroll
    for (int mt = 0; mt < 2; mt++)
#pragma unroll
        for (int nt = 0; nt < 4; nt++)
#pragma unroll
            for (int q = 0; q < 4; q++) acc[mt][nt][q] = 0.f;

    asm volatile("cp.async.wait_group 0;");
    __syncthreads();

#pragma unroll
    for (int ks = 0; ks < 8; ks++) {
        const int kc = ks * 16;
        unsigned bh2[2][4], bl2[2][4];
#pragma unroll
        for (int nh = 0; nh < 2; nh++) {
            const __half* pw = Wh + (kc + w_krow) * SA_W + wn * 32 + nh * 16 + w_noff;
            ldsm_x4t(bh2[nh], pw);
            const __half* pl = Wl + (kc + w_krow) * SA_W + wn * 32 + nh * 16 + w_noff;
            ldsm_x4t(bl2[nh], pl);
        }
#pragma unroll
        for (int mt = 0; mt < 2; mt++) {
            const int m0 = wm * 32 + mt * 16;
            unsigned a_[4];
            ldsm_x4(a_, As + (m0 + lr + a_row_off) * SA_A + kc + a_col_off);
#pragma unroll
            for (int nt = 0; nt < 4; nt++) {
                unsigned bhf[2] = {bh2[nt >> 1][(nt & 1) * 2],
                                   bh2[nt >> 1][(nt & 1) * 2 + 1]};
                unsigned blf[2] = {bl2[nt >> 1][(nt & 1) * 2],
                                   bl2[nt >> 1][(nt & 1) * 2 + 1]};
                mma16816(acc[mt][nt], a_, bhf);   // A @ Wh
                mma16816(acc[mt][nt], a_, blf);   // A @ Wl
            }
        }
    }

    // epilogue: scale by dinv (from deg), pack fp16, store
#pragma unroll
    for (int mt = 0; mt < 2; mt++) {
        int r0 = row0 + wm * 32 + mt * 16 + g;
        int r1 = r0 + 8;
        float d0 = (r0 < NN) ? rsqrtf((float)(g_deg[r0] + 1)) : 0.f;
        float d1 = (r1 < NN) ? rsqrtf((float)(g_deg[r1] + 1)) : 0.f;
#pragma unroll
        for (int nt = 0; nt < 4; nt++) {
            int n = col0 + wn * 32 + nt * 8 + t2;
            if (r0 < NN) {
                __half2 p = __floats2half2_rn(acc[mt][nt][0] * d0, acc[mt][nt][1] * d0);
                *(__half2*)(g_gh + (size_t)r0 * 128 + n) = p;
            }
            if (r1 < NN) {
                __half2 p = __floats2half2_rn(acc[mt][nt][2] * d1, acc[mt][nt][3] * d1);
                *(__half2*)(g_gh + (size_t)r1 * 128 + n) = p;
            }
        }
    }
}

// ---------------- aggregation (gather CSR; writes fp16 activations) ---------
__global__ void __launch_bounds__(256) k_agg(const float* __restrict__ bias) {
    int n = (blockIdx.x * blockDim.x + threadIdx.x) >> 5;
    int lane = threadIdx.x & 31;
    if (n >= NN) return;
    const uint2* gb = (const uint2*)g_gh;       // 8B units; row stride = 32
    uint2 sv = gb[(size_t)n * 32 + lane];       // self-loop term
    __half2 h0 = *(__half2*)&sv.x, h1 = *(__half2*)&sv.y;
    float2 f0 = __half22float2(h0), f1 = __half22float2(h1);
    float4 acc = make_float4(f0.x, f0.y, f1.x, f1.y);

    int s = g_off[n], e = g_off[n + 1];
    for (int base = s; base < e; base += 32) {
        int cnt = e - base; if (cnt > 32) cnt = 32;
        int id = (lane < cnt) ? g_csr[base + lane] : 0;
        int jmax = cnt & ~1;
        for (int j = 0; j < jmax; j += 2) {
            int sa = __shfl_sync(0xffffffffu, id, j);
            int sb = __shfl_sync(0xffffffffu, id, j + 1);
            uint2 va = gb[(size_t)sa * 32 + lane];
            uint2 vb = gb[(size_t)sb * 32 + lane];
            __half2 s0 = __hadd2(*(__half2*)&va.x, *(__half2*)&vb.x);
            __half2 s1 = __hadd2(*(__half2*)&va.y, *(__half2*)&vb.y);
            float2 g0 = __half22float2(s0), g1 = __half22float2(s1);
            acc.x += g0.x; acc.y += g0.y; acc.z += g1.x; acc.w += g1.y;
        }
        if (cnt & 1) {
            int sa = __shfl_sync(0xffffffffu, id, cnt - 1);
            uint2 va = gb[(size_t)sa * 32 + lane];
            float2 g0 = __half22float2(*(__half2*)&va.x);
            float2 g1 = __half22float2(*(__half2*)&va.y);
            acc.x += g0.x; acc.y += g0.y; acc.z += g1.x; acc.w += g1.y;
        }
    }
    float dn = rsqrtf((float)(g_deg[n] + 1));
    float4 bb = *(const float4*)(bias + lane * 4);
    __half2 o0 = __floats2half2_rn(acc.x * dn + bb.x, acc.y * dn + bb.y);
    __half2 o1 = __floats2half2_rn(acc.z * dn + bb.z, acc.w * dn + bb.w);
    uint2 p; p.x = *(unsigned*)&o0; p.y = *(unsigned*)&o1;
    *(uint2*)(g_ah + (size_t)n * 128 + lane * 4) = p;
}

// ---------------- mean pool per graph + output head -------------------------
__global__ void __launch_bounds__(128) k_pool(const int* __restrict__ batch,
                                              const float* __restrict__ Wout,
                                              const float* __restrict__ bout,
                                              float* __restrict__ out) {
    int gid = blockIdx.x;
    int c = threadIdx.x;
    int lo = 0, hi = NN;
    while (lo < hi) { int m = (lo + hi) >> 1; if (batch[m] < gid) lo = m + 1; else hi = m; }
    int start = lo;
    hi = NN;
    while (lo < hi) { int m = (lo + hi) >> 1; if (batch[m] < gid + 1) lo = m + 1; else hi = m; }
    int end = lo;

    float s = 0.f;
    for (int r = start; r < end; r++)
        s += __half2float(g_ah[(size_t)r * 128 + c]);
    __shared__ float pooled[128];
    int cnt = end - start;
    pooled[c] = (cnt > 0) ? s / (float)cnt : 0.f;
    __syncthreads();
    if (c < NOUT) {
        float a = bout[c];
#pragma unroll 8
        for (int k = 0; k < 128; k++) a += pooled[k] * Wout[k * NOUT + c];
        out[gid * NOUT + c] = a;
    }
}

// ---------------- launch (two-stream fork-join, capture-legal) ---------------
static cudaStream_t g_s2 = 0;
static cudaEvent_t  g_e0 = 0, g_e1 = 0, g_e2 = 0;

extern "C" void kernel_launch(void* const* d_in, const int* in_sizes, int n_in,
                              void* d_out, int out_size) {
    const float* x      = (const float*)d_in[0];
    const int*   ei     = (const int*)d_in[1];     // int32 (JAX x64 disabled)
    const int*   batch  = (const int*)d_in[2];     // int32
    const float* W_in   = (const float*)d_in[3];
    const float* b_in   = (const float*)d_in[4];
    const float* W_hid  = (const float*)d_in[5];
    const float* b_hid  = (const float*)d_in[6];
    const float* W_out  = (const float*)d_in[7];
    const float* b_out  = (const float*)d_in[8];
    float* out = (float*)d_out;

    if (!g_s2) {   // first call is the (non-captured) correctness run
        cudaStreamCreateWithFlags(&g_s2, cudaStreamNonBlocking);
        cudaEventCreateWithFlags(&g_e0, cudaEventDisableTiming);
        cudaEventCreateWithFlags(&g_e1, cudaEventDisableTiming);
        cudaEventCreateWithFlags(&g_e2, cudaEventDisableTiming);
        cudaFuncSetAttribute(k_gemm_tc, cudaFuncAttributeMaxDynamicSharedMemorySize,
                             SMEM_BYTES);
    }

    const int gemm_blocks = ((NN + 127) / 128) * 2;   // 128x64 tiles
    const int agg_blocks  = (NN * 32 + 255) / 256;

    // default stream: zero -> conv -> (deg ready) gemm0 -> (csr ready) agg...
    // s2 (forked):    edge_prep -> scan -> fill
    k_zero<<<NB_ZERO, 256>>>();
    cudaEventRecord(g_e0, 0);
    cudaStreamWaitEvent(g_s2, g_e0, 0);

    k_edge_prep<<<(NE / 4 + 255) / 256, 256, 0, g_s2>>>(ei);
    cudaEventRecord(g_e1, g_s2);                      // deg final
    k_scan_fused<<<NB_SCAN, 1024, 0, g_s2>>>();
    k_fill<<<(NE / 4 + 255) / 256, 256, 0, g_s2>>>(ei);
    cudaEventRecord(g_e2, g_s2);                      // csr final

    k_conv<<<NB_XCONV + 64, 256>>>(x, W_in, W_hid);   // overlaps edge_prep
    cudaStreamWaitEvent(0, g_e1, 0);
    k_gemm_tc<<<gemm_blocks, 256, SMEM_BYTES>>>(0);   // overlaps scan+fill
    cudaStreamWaitEvent(0, g_e2, 0);                  // join before agg

    k_agg<<<agg_blocks, 256>>>(b_in);
    for (int i = 0; i < 3; i++) {
        k_gemm_tc<<<gemm_blocks, 256, SMEM_BYTES>>>(i + 1);
        k_agg<<<agg_blocks, 256>>>(b_hid + (size_t)i * 128);
    }

    k_pool<<<NG, 128>>>(batch, W_out, b_out, out);
}

// round 14
// speedup vs baseline: 1.2762x; 1.0397x over previous
#include <cuda_runtime.h>
#include <cuda_fp16.h>

#define NN 100000
#define NE 1600000
#define NG 512
#define NOUT 10
#define NB_SCAN ((NN + 1023) / 1024)     // 98
#define NB_ZERO ((NN + 255) / 256)       // 391
#define NB_EDGE ((NE / 4 + 255) / 256)   // 1563
#define NB_XCONV 12500                   // NN*128/4/256

// GEMM geometry: CTA = 128x64 output, 8 warps (4x2), warp tile 32x32.
// Whole K=128 resident in smem: A fp16 [128][136], W hi/lo [128][72] each.
#define SA_A 136                         // A smem row stride (halves)
#define SA_W 72                          // W smem row stride (halves)
#define A_HALVES (128 * SA_A)            // 17408
#define W_HALVES (128 * SA_W)            // 9216
#define SMEM_BYTES ((A_HALVES + 2 * W_HALVES) * 2)   // 71680 B

// ---------------- scratch (device globals; no allocation allowed) ----------
__device__ __align__(16) __half g_gh[(size_t)NN * 128];   // g = dinv*(h@W), fp16
__device__ __align__(16) __half g_ah[(size_t)NN * 128];   // activations, fp16
__device__ __align__(16) __half g_wh[4 * 128 * 128];      // weights hi (4 layers)
__device__ __align__(16) __half g_wl[4 * 128 * 128];      // weights lo
__device__ __align__(16) int    g_deg[NN];
__device__ __align__(16) int    g_fill[NN];
__device__ __align__(16) int    g_off[NN + 1];
__device__ __align__(16) unsigned long long g_scanstate[128];
__device__ __align__(16) int    g_csr[NE];

// ---------------- helpers ----------------------------------------------------
__device__ __forceinline__ void split2(float a, float b, unsigned& hi, unsigned& lo) {
    __half h0 = __float2half_rn(a), h1 = __float2half_rn(b);
    __half l0 = __float2half_rn(a - __half2float(h0));
    __half l1 = __float2half_rn(b - __half2float(h1));
    __half2 H = __halves2half2(h0, h1), L = __halves2half2(l0, l1);
    hi = *(unsigned*)&H; lo = *(unsigned*)&L;
}

__device__ __forceinline__ void mma16816(float* c, const unsigned* a, const unsigned* b) {
    asm volatile(
        "mma.sync.aligned.m16n8k16.row.col.f32.f16.f16.f32 "
        "{%0,%1,%2,%3}, {%4,%5,%6,%7}, {%8,%9}, {%0,%1,%2,%3};"
        : "+f"(c[0]), "+f"(c[1]), "+f"(c[2]), "+f"(c[3])
        : "r"(a[0]), "r"(a[1]), "r"(a[2]), "r"(a[3]), "r"(b[0]), "r"(b[1]));
}

__device__ __forceinline__ void cpa16(__half* dst_smem, const __half* src) {
    unsigned d = (unsigned)__cvta_generic_to_shared(dst_smem);
    asm volatile("cp.async.cg.shared.global [%0], [%1], 16;" :: "r"(d), "l"(src));
}

__device__ __forceinline__ void ldsm_x4(unsigned* r, const __half* p) {
    unsigned a = (unsigned)__cvta_generic_to_shared(p);
    asm volatile("ldmatrix.sync.aligned.m8n8.x4.shared.b16 {%0,%1,%2,%3}, [%4];"
                 : "=r"(r[0]), "=r"(r[1]), "=r"(r[2]), "=r"(r[3]) : "r"(a));
}

__device__ __forceinline__ void ldsm_x4t(unsigned* r, const __half* p) {
    unsigned a = (unsigned)__cvta_generic_to_shared(p);
    asm volatile("ldmatrix.sync.aligned.m8n8.x4.trans.shared.b16 {%0,%1,%2,%3}, [%4];"
                 : "=r"(r[0]), "=r"(r[1]), "=r"(r[2]), "=r"(r[3]) : "r"(a));
}

// ---------------- zero: deg + scan state -------------------------------------
__global__ void k_zero() {
    int i = blockIdx.x * 256 + threadIdx.x;
    if (i < NN) g_deg[i] = 0;
    if (blockIdx.x == 0 && threadIdx.x < 128) g_scanstate[threadIdx.x] = 0ULL;
}

// ---------------- fused prep: edge atomics + x conv + W split ----------------
// Atomic-latency-bound warps (edges) interleave with BW-bound warps (conv) in
// one kernel — genuine resource overlap that streams could not deliver.
__global__ void k_prep(const int* __restrict__ ei,
                       const float* __restrict__ x,
                       const float* __restrict__ W_in,
                       const float* __restrict__ W_hid) {
    int b = blockIdx.x;
    if (b < NB_EDGE) {
        int t = b * 256 + threadIdx.x;
        if (t < NE / 4) {
            int4 d = ((const int4*)(ei + NE))[t];
            atomicAdd(&g_deg[d.x], 1);
            atomicAdd(&g_deg[d.y], 1);
            atomicAdd(&g_deg[d.z], 1);
            atomicAdd(&g_deg[d.w], 1);
        }
    } else if (b < NB_EDGE + NB_XCONV) {
        size_t i = (size_t)(b - NB_EDGE) * 256 + threadIdx.x;   // float4 index
        float4 v = ((const float4*)x)[i];
        __half2 a = __floats2half2_rn(v.x, v.y);
        __half2 c = __floats2half2_rn(v.z, v.w);
        uint2 p; p.x = *(unsigned*)&a; p.y = *(unsigned*)&c;
        *(uint2*)(g_ah + i * 4) = p;
    } else {
        size_t wi = (size_t)(b - NB_EDGE - NB_XCONV) * 256 + threadIdx.x;
        if (wi < 16384) {
            float4 v = (wi < 4096) ? ((const float4*)W_in)[wi]
                                   : ((const float4*)W_hid)[wi - 4096];
            uint2 hi, lo;
            split2(v.x, v.y, hi.x, lo.x);
            split2(v.z, v.w, hi.y, lo.y);
            *(uint2*)(g_wh + wi * 4) = hi;
            *(uint2*)(g_wl + wi * 4) = lo;
        }
    }
}

// ---------------- fused scan (decoupled lookback): off + fill seed ----------
__global__ void k_scan_fused() {
    __shared__ int sm[1024];
    __shared__ int s_prefix;
    const int b = blockIdx.x;
    const int i = b * 1024 + threadIdx.x;
    const int v = (i < NN) ? g_deg[i] : 0;
    sm[threadIdx.x] = v;
    __syncthreads();
    for (int d = 1; d < 1024; d <<= 1) {
        int t = (threadIdx.x >= d) ? sm[threadIdx.x - d] : 0;
        __syncthreads();
        sm[threadIdx.x] += t;
        __syncthreads();
    }
    if (threadIdx.x == 0) {
        const unsigned total = (unsigned)sm[1023];
        if (b == 0) {
            atomicExch(&g_scanstate[0], (2ULL << 32) | total);   // inclusive
            s_prefix = 0;
        } else {
            atomicExch(&g_scanstate[b], (1ULL << 32) | total);   // aggregate
            int excl = 0;
            int pb = b - 1;
            while (true) {
                unsigned long long st = atomicAdd(&g_scanstate[pb], 0ULL);
                unsigned flag = (unsigned)(st >> 32);
                if (flag == 0) continue;                          // spin
                excl += (int)(st & 0xffffffffu);
                if (flag == 2u) break;
                pb--;
            }
            atomicExch(&g_scanstate[b], (2ULL << 32) | (unsigned)(total + excl));
            s_prefix = excl;
        }
    }
    __syncthreads();
    const int incl = sm[threadIdx.x] + s_prefix;
    if (i < NN) {
        int excl_i = incl - v;
        g_off[i]  = excl_i;
        g_fill[i] = excl_i;
        if (i == NN - 1) g_off[NN] = incl;
    }
}

__global__ void k_fill(const int* __restrict__ ei) {
    int t = blockIdx.x * blockDim.x + threadIdx.x;
    if (t < NE / 4) {
        int4 s = ((const int4*)ei)[t];
        int4 d = ((const int4*)(ei + NE))[t];
        int p;
        p = atomicAdd(&g_fill[d.x], 1); g_csr[p] = s.x;
        p = atomicAdd(&g_fill[d.y], 1); g_csr[p] = s.y;
        p = atomicAdd(&g_fill[d.z], 1); g_csr[p] = s.z;
        p = atomicAdd(&g_fill[d.w], 1); g_csr[p] = s.w;
    }
}

// ---------------- tensor-core GEMM: g = fp16( dinv * (A @ W) ) ---------------
// Whole-K resident: one cp.async burst, one wait, one sync, then 8 k-steps of
// MMA with zero barriers. A fp16; W split hi/lo (2-term MMA).
// CTA = 128x64; 8 warps 4x2, warp tile 32x32. 3 CTAs/SM.
__global__ void __launch_bounds__(256, 3) k_gemm_tc(int layer) {
    extern __shared__ __half smh[];
    __half* As = smh;                        // [128][SA_A]
    __half* Wh = smh + A_HALVES;             // [128][SA_W]
    __half* Wl = smh + A_HALVES + W_HALVES;  // [128][SA_W]
    const int col0 = (blockIdx.x & 1) * 64;
    const int row0 = (blockIdx.x >> 1) * 128;
    const __half* Wbh = g_wh + (size_t)layer * 16384 + col0;
    const __half* Wbl = g_wl + (size_t)layer * 16384 + col0;
    const int tid = threadIdx.x;

    // single burst: whole A tile (128x128) + whole W hi/lo (128x64 each)
#pragma unroll
    for (int o = tid; o < 2048; o += 256) {           // A: 128 rows x 16 segs
        int r = o >> 4, seg = (o & 15) * 8;
        int grow = row0 + r;
        if (grow < NN)
            cpa16(As + r * SA_A + seg, g_ah + (size_t)grow * 128 + seg);
    }
#pragma unroll
    for (int o = tid; o < 2048; o += 256) {           // W: 128 rows x 8 segs x2
        int oo = o & 1023;
        int kr = oo >> 3, seg = (oo & 7) * 8;
        if (o < 1024)
            cpa16(Wh + kr * SA_W + seg, Wbh + (size_t)kr * 128 + seg);
        else
            cpa16(Wl + kr * SA_W + seg, Wbl + (size_t)kr * 128 + seg);
    }
    asm volatile("cp.async.commit_group;");

    const int lane = tid & 31, wid = tid >> 5;
    const int wm = wid >> 1, wn = wid & 1;               // 4x2 warp grid
    const int g = lane >> 2, t2 = (lane & 3) << 1;
    const int lr = lane & 7, sel = lane >> 3;
    const int a_row_off = (sel & 1) * 8;
    const int a_col_off = (sel & 2) * 4;
    const int w_krow = lane & 15;
    const int w_noff = (lane >> 4) * 8;

    float acc[2][4][4];
#pragma unroll
    for (int mt = 0; mt < 2; mt++)
#pragma unroll
        for (int nt = 0; nt < 4; nt++)
#pragma unroll
            for (int q = 0; q < 4; q++) acc[mt][nt][q] = 0.f;

    asm volatile("cp.async.wait_group 0;");
    __syncthreads();

#pragma unroll
    for (int ks = 0; ks < 8; ks++) {
        const int kc = ks * 16;
        unsigned bh2[2][4], bl2[2][4];
#pragma unroll
        for (int nh = 0; nh < 2; nh++) {
            const __half* pw = Wh + (kc + w_krow) * SA_W + wn * 32 + nh * 16 + w_noff;
            ldsm_x4t(bh2[nh], pw);
            const __half* pl = Wl + (kc + w_krow) * SA_W + wn * 32 + nh * 16 + w_noff;
            ldsm_x4t(bl2[nh], pl);
        }
#pragma unroll
        for (int mt = 0; mt < 2; mt++) {
            const int m0 = wm * 32 + mt * 16;
            unsigned a_[4];
            ldsm_x4(a_, As + (m0 + lr + a_row_off) * SA_A + kc + a_col_off);
#pragma unroll
            for (int nt = 0; nt < 4; nt++) {
                unsigned bhf[2] = {bh2[nt >> 1][(nt & 1) * 2],
                                   bh2[nt >> 1][(nt & 1) * 2 + 1]};
                unsigned blf[2] = {bl2[nt >> 1][(nt & 1) * 2],
                                   bl2[nt >> 1][(nt & 1) * 2 + 1]};
                mma16816(acc[mt][nt], a_, bhf);   // A @ Wh
                mma16816(acc[mt][nt], a_, blf);   // A @ Wl
            }
        }
    }

    // epilogue: scale by dinv (from deg), pack fp16, store
#pragma unroll
    for (int mt = 0; mt < 2; mt++) {
        int r0 = row0 + wm * 32 + mt * 16 + g;
        int r1 = r0 + 8;
        float d0 = (r0 < NN) ? rsqrtf((float)(g_deg[r0] + 1)) : 0.f;
        float d1 = (r1 < NN) ? rsqrtf((float)(g_deg[r1] + 1)) : 0.f;
#pragma unroll
        for (int nt = 0; nt < 4; nt++) {
            int n = col0 + wn * 32 + nt * 8 + t2;
            if (r0 < NN) {
                __half2 p = __floats2half2_rn(acc[mt][nt][0] * d0, acc[mt][nt][1] * d0);
                *(__half2*)(g_gh + (size_t)r0 * 128 + n) = p;
            }
            if (r1 < NN) {
                __half2 p = __floats2half2_rn(acc[mt][nt][2] * d1, acc[mt][nt][3] * d1);
                *(__half2*)(g_gh + (size_t)r1 * 128 + n) = p;
            }
        }
    }
}

// ---------------- aggregation (gather CSR; 4 edges in flight) ---------------
__global__ void __launch_bounds__(256) k_agg(const float* __restrict__ bias) {
    int n = (blockIdx.x * blockDim.x + threadIdx.x) >> 5;
    int lane = threadIdx.x & 31;
    if (n >= NN) return;
    const uint2* gb = (const uint2*)g_gh;       // 8B units; row stride = 32
    uint2 sv = gb[(size_t)n * 32 + lane];       // self-loop term
    __half2 h0 = *(__half2*)&sv.x, h1 = *(__half2*)&sv.y;
    float2 f0 = __half22float2(h0), f1 = __half22float2(h1);
    float4 acc = make_float4(f0.x, f0.y, f1.x, f1.y);

    int s = g_off[n], e = g_off[n + 1];
    for (int base = s; base < e; base += 32) {
        int cnt = e - base; if (cnt > 32) cnt = 32;
        int id = (lane < cnt) ? g_csr[base + lane] : 0;
        int j = 0;
        for (; j + 4 <= cnt; j += 4) {          // two independent HADD2 pairs
            int s0 = __shfl_sync(0xffffffffu, id, j);
            int s1 = __shfl_sync(0xffffffffu, id, j + 1);
            int s2 = __shfl_sync(0xffffffffu, id, j + 2);
            int s3 = __shfl_sync(0xffffffffu, id, j + 3);
            uint2 va = gb[(size_t)s0 * 32 + lane];
            uint2 vb = gb[(size_t)s1 * 32 + lane];
            uint2 vc = gb[(size_t)s2 * 32 + lane];
            uint2 vd = gb[(size_t)s3 * 32 + lane];
            __half2 p0 = __hadd2(*(__half2*)&va.x, *(__half2*)&vb.x);
            __half2 p1 = __hadd2(*(__half2*)&va.y, *(__half2*)&vb.y);
            __half2 q0 = __hadd2(*(__half2*)&vc.x, *(__half2*)&vd.x);
            __half2 q1 = __hadd2(*(__half2*)&vc.y, *(__half2*)&vd.y);
            float2 a0 = __half22float2(p0), a1 = __half22float2(p1);
            float2 b0 = __half22float2(q0), b1 = __half22float2(q1);
            acc.x += a0.x + b0.x; acc.y += a0.y + b0.y;
            acc.z += a1.x + b1.x; acc.w += a1.y + b1.y;
        }
        if (j + 2 <= cnt) {
            int s0 = __shfl_sync(0xffffffffu, id, j);
            int s1 = __shfl_sync(0xffffffffu, id, j + 1);
            uint2 va = gb[(size_t)s0 * 32 + lane];
            uint2 vb = gb[(size_t)s1 * 32 + lane];
            __half2 p0 = __hadd2(*(__half2*)&va.x, *(__half2*)&vb.x);
            __half2 p1 = __hadd2(*(__half2*)&va.y, *(__half2*)&vb.y);
            float2 a0 = __half22float2(p0), a1 = __half22float2(p1);
            acc.x += a0.x; acc.y += a0.y; acc.z += a1.x; acc.w += a1.y;
            j += 2;
        }
        if (j < cnt) {
            int s0 = __shfl_sync(0xffffffffu, id, j);
            uint2 va = gb[(size_t)s0 * 32 + lane];
            float2 a0 = __half22float2(*(__half2*)&va.x);
            float2 a1 = __half22float2(*(__half2*)&va.y);
            acc.x += a0.x; acc.y += a0.y; acc.z += a1.x; acc.w += a1.y;
        }
    }
    float dn = rsqrtf((float)(g_deg[n] + 1));
    float4 bb = *(const float4*)(bias + lane * 4);
    __half2 o0 = __floats2half2_rn(acc.x * dn + bb.x, acc.y * dn + bb.y);
    __half2 o1 = __floats2half2_rn(acc.z * dn + bb.z, acc.w * dn + bb.w);
    uint2 p; p.x = *(unsigned*)&o0; p.y = *(unsigned*)&o1;
    *(uint2*)(g_ah + (size_t)n * 128 + lane * 4) = p;
}

// ---------------- mean pool per graph + output head -------------------------
__global__ void __launch_bounds__(128) k_pool(const int* __restrict__ batch,
                                              const float* __restrict__ Wout,
                                              const float* __restrict__ bout,
                                              float* __restrict__ out) {
    int gid = blockIdx.x;
    int c = threadIdx.x;
    int lo = 0, hi = NN;
    while (lo < hi) { int m = (lo + hi) >> 1; if (batch[m] < gid) lo = m + 1; else hi = m; }
    int start = lo;
    hi = NN;
    while (lo < hi) { int m = (lo + hi) >> 1; if (batch[m] < gid + 1) lo = m + 1; else hi = m; }
    int end = lo;

    float s = 0.f;
    for (int r = start; r < end; r++)
        s += __half2float(g_ah[(size_t)r * 128 + c]);
    __shared__ float pooled[128];
    int cnt = end - start;
    pooled[c] = (cnt > 0) ? s / (float)cnt : 0.f;
    __syncthreads();
    if (c < NOUT) {
        float a = bout[c];
#pragma unroll 8
        for (int k = 0; k < 128; k++) a += pooled[k] * Wout[k * NOUT + c];
        out[gid * NOUT + c] = a;
    }
}

// ---------------- launch (single stream; fused prep) -------------------------
extern "C" void kernel_launch(void* const* d_in, const int* in_sizes, int n_in,
                              void* d_out, int out_size) {
    const float* x      = (const float*)d_in[0];
    const int*   ei     = (const int*)d_in[1];     // int32 (JAX x64 disabled)
    const int*   batch  = (const int*)d_in[2];     // int32
    const float* W_in   = (const float*)d_in[3];
    const float* b_in   = (const float*)d_in[4];
    const float* W_hid  = (const float*)d_in[5];
    const float* b_hid  = (const float*)d_in[6];
    const float* W_out  = (const float*)d_in[7];
    const float* b_out  = (const float*)d_in[8];
    float* out = (float*)d_out;

    cudaFuncSetAttribute(k_gemm_tc, cudaFuncAttributeMaxDynamicSharedMemorySize,
                         SMEM_BYTES);

    const int gemm_blocks = ((NN + 127) / 128) * 2;   // 128x64 tiles
    const int agg_blocks  = (NN * 32 + 255) / 256;

    // gemm0 kept as 4th launch (ncu capture slot)
    k_zero<<<NB_ZERO, 256>>>();
    k_prep<<<NB_EDGE + NB_XCONV + 64, 256>>>(ei, x, W_in, W_hid);
    k_scan_fused<<<NB_SCAN, 1024>>>();
    k_gemm_tc<<<gemm_blocks, 256, SMEM_BYTES>>>(0);          // <- profiled
    k_fill<<<NB_EDGE, 256>>>(ei);

    k_agg<<<agg_blocks, 256>>>(b_in);
    for (int i = 0; i < 3; i++) {
        k_gemm_tc<<<gemm_blocks, 256, SMEM_BYTES>>>(i + 1);
        k_agg<<<agg_blocks, 256>>>(b_hid + (size_t)i * 128);
    }

    k_pool<<<NG, 128>>>(batch, W_out, b_out, out);
}